// round 16
// baseline (speedup 1.0000x reference)
#include <cuda_runtime.h>
#include <cuda_fp16.h>
#include <math.h>
#include <float.h>
#include <stdint.h>

// ---------------- problem constants ----------------
#define N_POS 16384      // B*H*W
#define DIM   128
#define HW    1024
#define ZQ_ELEMS 2097152
#define LOSS_OFF 2097152
#define IDX_OFF  2097153
#define KCB   8192
#define N_UNITS 8192     // 128 tiles * 64 chunks
#define N_CTAS 148       // persistent grid: one CTA per SM
#define CAND_STRIDE 48   // max candidate keys per query (<=3 segments * 16)
#define DELTA 5.0e-3f    // admit margin: 2*fp16 dot err + 2*key quantization

// ---------------- device scratch ----------------
__device__ float g_znorm[(size_t)N_POS * DIM];    // [n][c] for exact rescore
__device__ float g_znorm_t[(size_t)ZQ_ELEMS];     // [b][c][hw] for coalesced scatter
__device__ __align__(16) float g_cs2[KCB];        // 2.0 + 0.5*||c||^2
__device__ int   g_idx[N_POS];
__device__ float g_lossacc;
__device__ unsigned g_done;                       // scatter completion ticket
__device__ int   g_ccnt[N_POS];
__device__ int   g_cand[(size_t)N_POS * CAND_STRIDE];
__device__ __align__(16) __half g_wh[(size_t)KCB * DIM];
__device__ __align__(16) __half g_zh[(size_t)N_POS * DIM];

// ---------------- smem layout (bytes) ----------------
#define ROW_B   272              // 136 halves per row (68 words %32==4 -> conflict-free)
#define TILE_B  34816            // 128 * 272
#define AH_B    0
#define BH_B    34816            // + buf*TILE_B
#define CS_B    104448           // float [2][128]
#define SBASE_B 105472           // int [128] flush slot bases
#define SM_TOTAL 105984

// ---------------- PTX helpers (sm_80-compatible only) ----------------
#define CP16(dst, src) \
    asm volatile("cp.async.cg.shared.global [%0], [%1], 16;" \
                 :: "r"(dst), "l"(src) : "memory")
#define CP_COMMIT() asm volatile("cp.async.commit_group;" ::: "memory")
#define CP_WAIT1()  asm volatile("cp.async.wait_group 1;" ::: "memory")
#define CP_WAIT0()  asm volatile("cp.async.wait_group 0;" ::: "memory")

#define LDMATRIX_X4(r0, r1, r2, r3, addr) \
    asm volatile("ldmatrix.sync.aligned.m8n8.x4.shared.b16 {%0,%1,%2,%3}, [%4];" \
                 : "=r"(r0), "=r"(r1), "=r"(r2), "=r"(r3) : "r"(addr))

__device__ __forceinline__ uint32_t smem_u32(const void* p) {
    uint32_t a;
    asm("{ .reg .u64 t; cvta.to.shared.u64 t, %1; cvt.u32.u64 %0, t; }" : "=r"(a) : "l"(p));
    return a;
}

__device__ __forceinline__ void mma16816(float* c, const uint32_t* a, const uint32_t* b) {
    asm volatile(
        "mma.sync.aligned.m16n8k16.row.col.f32.f16.f16.f32 "
        "{%0,%1,%2,%3}, {%4,%5,%6,%7}, {%8,%9}, {%0,%1,%2,%3};"
        : "+f"(c[0]), "+f"(c[1]), "+f"(c[2]), "+f"(c[3])
        : "r"(a[0]), "r"(a[1]), "r"(a[2]), "r"(a[3]), "r"(b[0]), "r"(b[1]));
}

// TwoSum accumulate: (s, c) += x, error-free
__device__ __forceinline__ void ds_add(float& s, float& c, float x) {
    float t = s + x;
    float bb = t - s;
    float err = (s - (t - bb)) + (x - bb);
    s = t;
    c += err;
}

// ---------------------------------------------------------------------------
// Fused prep kernel. 1152 blocks x 256 threads, role by blockIdx:
//   [0,64)        : L2 normalize 256 positions/block -> znorm, znorm_t, zh
//   [64,1088)     : codebook prep, warp-per-row (coalesced float4) -> wh, cs2
//   [1088,1152)   : reset candidate counters + loss accumulator
// ---------------------------------------------------------------------------
__global__ void k_prep(const float* __restrict__ z, const float* __restrict__ w) {
    int blk = blockIdx.x;
    int t = threadIdx.x;

    if (blk < 64) {
        int b   = blk >> 2;
        int col = ((blk & 3) << 8) + t;
        const float* zb = z + (size_t)b * (DIM * HW);

        float s = 0.0f;
#pragma unroll 8
        for (int c = 0; c < DIM; c++) {
            float v = zb[c * HW + col];
            s = fmaf(v, v, s);
        }
        float den = fmaxf(sqrtf(s), 1e-12f);

        int n = b * HW + col;
        float* zn = g_znorm + (size_t)n * DIM;
        float* znt = g_znorm_t + (size_t)b * (DIM * HW);
        __half* zh = g_zh + (size_t)n * DIM;
#pragma unroll
        for (int c8 = 0; c8 < 16; c8++) {
            __align__(16) __half hb[8];
#pragma unroll
            for (int j = 0; j < 8; j++) {
                int c = c8 * 8 + j;
                float wv = zb[c * HW + col] / den;
                zn[c] = wv;
                znt[c * HW + col] = wv;
                hb[j] = __float2half_rn(wv);
            }
            *(uint4*)(zh + c8 * 8) = *(uint4*)hb;
        }
    } else if (blk < 1088) {
        int lane = t & 31;
        int row = (blk - 64) * 8 + (t >> 5);
        float4 v = ((const float4*)(w + (size_t)row * DIM))[lane];

        __half2 h0 = __floats2half2_rn(v.x, v.y);
        __half2 h1 = __floats2half2_rn(v.z, v.w);
        uint2 packed = make_uint2(*(uint32_t*)&h0, *(uint32_t*)&h1);
        *(uint2*)(g_wh + (size_t)row * DIM + lane * 4) = packed;

        float sq = v.x * v.x + v.y * v.y + v.z * v.z + v.w * v.w;
#pragma unroll
        for (int off = 16; off; off >>= 1) sq += __shfl_down_sync(0xffffffffu, sq, off);
        if (lane == 0) g_cs2[row] = 2.0f + 0.5f * sq;
    } else {
        int n = (blk - 1088) * 256 + t;
        g_ccnt[n] = 0;
        if (n == 0) g_lossacc = 0.0f;
    }
}

// ---------------------------------------------------------------------------
// 128-code chunk cp.async issue (Bh tile + cs2 floats), 256 threads
// ---------------------------------------------------------------------------
__device__ __forceinline__ void issue_b(uint32_t sb, int buf, int chunk, int tid) {
    const char* srcH = (const char*)(g_wh + (size_t)chunk * 128 * DIM);
    uint32_t dH = sb + BH_B + buf * TILE_B;
#pragma unroll
    for (int r = 0; r < 8; r++) {
        int c = tid + 256 * r;          // 0..2047
        int row = c >> 4;
        int off = (c & 15) * 16;
        CP16(dH + row * ROW_B + off, srcH + row * 256 + off);
    }
    if (tid < 32)
        CP16(sb + CS_B + buf * 512 + tid * 16,
             (const char*)g_cs2 + (size_t)chunk * 512 + tid * 16);
}

// ---------------------------------------------------------------------------
// Main: persistent K-split. 148 CTAs x 256 threads; CTA g owns contiguous
// work units [g*8192/148, (g+1)*8192/148), unit = tile*64 + chunk.
// f32-accum HMMA screen + packed-key top-2; flush 16 holder keys/query.
// ---------------------------------------------------------------------------
__global__ __launch_bounds__(256, 1)
void k_main_split(float* __restrict__ dout) {
    extern __shared__ __align__(16) unsigned char smem[];

    const int tid  = threadIdx.x;
    const int lane = tid & 31;
    const int wid  = tid >> 5;
    const int wm = wid & 3, wn = wid >> 2;
    const int gp = lane >> 2, qd = lane & 3;
    const int g = blockIdx.x;

    uint32_t sb = smem_u32(smem);
    int* sbase = (int*)(smem + SBASE_B);

    const uint32_t a_row = (uint32_t)(wm * 32 + (lane & 7) + ((lane >> 3) & 1) * 8);
    const uint32_t a_colb = (uint32_t)((lane >> 4) * 16);
    const uint32_t aoff0 = sb + AH_B + a_row * ROW_B + a_colb;
    const uint32_t b_row = (uint32_t)(wn * 64 + ((lane >> 4) ? 8 : 0) + (lane & 7));
    const uint32_t b_colb = (uint32_t)(((lane >> 3) & 1) * 16);
    const uint32_t boff0 = b_row * ROW_B + b_colb;

    int u  = (int)((long long)g * N_UNITS / N_CTAS);
    int u1 = (int)((long long)(g + 1) * N_UNITS / N_CTAS);

    while (u < u1) {
        int tile = u >> 6;
        int cs = u & 63;
        int ce = min(64, cs + (u1 - u));
        int q0 = tile << 7;

        {
            const char* srcH = (const char*)(g_zh + (size_t)q0 * DIM);
#pragma unroll
            for (int r = 0; r < 8; r++) {
                int c = tid + 256 * r;
                int row = c >> 4;
                int off = (c & 15) * 16;
                CP16(sb + AH_B + row * ROW_B + off, srcH + row * 256 + off);
            }
            CP_COMMIT();
        }
        issue_b(sb, 0, cs, tid); CP_COMMIT();
        if (cs + 1 < ce) issue_b(sb, 1, cs + 1, tid);
        CP_COMMIT();

        int k1[4], k2[4];
#pragma unroll
        for (int s = 0; s < 4; s++) { k1[s] = 0x7fffffff; k2[s] = 0x7fffffff; }

        for (int c = cs; c < ce; c++) {
            int cur = (c - cs) & 1;
            if (c < ce - 1) CP_WAIT1(); else CP_WAIT0();
            __syncthreads();

            uint32_t bbase = sb + BH_B + cur * TILE_B + boff0;

            float acc[2][8][4];
#pragma unroll
            for (int mi = 0; mi < 2; mi++)
#pragma unroll
                for (int ni = 0; ni < 8; ni++)
#pragma unroll
                    for (int v = 0; v < 4; v++) acc[mi][ni][v] = 0.0f;

#pragma unroll
            for (int ks = 0; ks < 8; ks++) {
                uint32_t kb = (uint32_t)(ks * 32);
                uint32_t a[2][4], b[8][2];
#pragma unroll
                for (int mi = 0; mi < 2; mi++)
                    LDMATRIX_X4(a[mi][0], a[mi][1], a[mi][2], a[mi][3],
                                aoff0 + (uint32_t)(mi * 16 * ROW_B) + kb);
#pragma unroll
                for (int gq = 0; gq < 4; gq++)
                    LDMATRIX_X4(b[2 * gq][0], b[2 * gq][1], b[2 * gq + 1][0], b[2 * gq + 1][1],
                                bbase + (uint32_t)(gq * 16 * ROW_B) + kb);
#pragma unroll
                for (int mi = 0; mi < 2; mi++)
#pragma unroll
                    for (int ni = 0; ni < 8; ni++)
                        mma16816(acc[mi][ni], a[mi], b[ni]);
            }

            const float* csf = (const float*)(smem + CS_B + cur * 512);
            int cbase = c * 128 + wn * 64 + qd * 2;
#pragma unroll
            for (int ni = 0; ni < 8; ni++) {
                float2 c2 = *(const float2*)(csf + wn * 64 + ni * 8 + qd * 2);
                int c0 = cbase + ni * 8;
                int c1 = c0 + 1;
#pragma unroll
                for (int mi = 0; mi < 2; mi++)
#pragma unroll
                    for (int v = 0; v < 4; v++) {
                        float m = ((v & 1) ? c2.y : c2.x) - acc[mi][ni][v];
                        int key = (int)((__float_as_uint(m) & 0xFFFFE000u) |
                                        (uint32_t)((v & 1) ? c1 : c0));
                        int s = mi * 2 + (v >> 1);
                        int lo = min(key, k1[s]);
                        int hi = max(key, k1[s]);
                        k1[s] = lo;
                        k2[s] = min(k2[s], hi);
                    }
            }

            __syncthreads();
            if (c + 2 < ce) { issue_b(sb, cur, c + 2, tid); CP_COMMIT(); }
        }

        if (tid < 128) {
            int base = atomicAdd(&g_ccnt[q0 + tid], 16);
            sbase[tid] = min(base, CAND_STRIDE - 16);
        }
        __syncthreads();
#pragma unroll
        for (int s = 0; s < 4; s++) {
            int row = wm * 32 + (s >> 1) * 16 + (s & 1) * 8 + gp;
            int* dst = g_cand + (size_t)(q0 + row) * CAND_STRIDE + sbase[row] + (wn * 4 + qd) * 2;
            dst[0] = k1[s];
            dst[1] = k2[s];
        }
        __syncthreads();

        u += ce - cs;
    }
}

// ---------------------------------------------------------------------------
// Merge: per query, global min over candidates, admit within DELTA, exact
// rescore in double-single (compensated fp32).
// ---------------------------------------------------------------------------
__global__ void k_merge(const float* __restrict__ weight, float* __restrict__ dout) {
    int n = blockIdx.x * 128 + threadIdx.x;
    int cnt = min(g_ccnt[n], CAND_STRIDE);
    const int* cand = g_cand + (size_t)n * CAND_STRIDE;

    int mink = 0x7fffffff;
    for (int e = 0; e < cnt; e++) mink = min(mink, cand[e]);

    float cut = __uint_as_float((uint32_t)mink & 0xFFFFE000u) + DELTA;
    int ck[CAND_STRIDE]; int cc = 0;
    for (int e = 0; e < cnt; e++) {
        int key = cand[e];
        if (key != 0x7fffffff &&
            __uint_as_float((uint32_t)key & 0xFFFFE000u) <= cut)
            ck[cc++] = key & 0x1FFF;
    }

    int best;
    if (cc == 1) {
        best = ck[0];
    } else {
        const float4* zr = (const float4*)(g_znorm + (size_t)n * DIM);
        double bq = 1e300; best = 0x7fffffff;
        for (int e = 0; e < cc; e++) {
            int k = ck[e];
            const float4* wr = (const float4*)(weight + (size_t)k * DIM);
            float s = 0.0f, comp = 0.0f;
#pragma unroll 4
            for (int d4 = 0; d4 < DIM / 4; d4++) {
                float4 wv = wr[d4];
                float4 zv = zr[d4];
                float wa[4] = { wv.x, wv.y, wv.z, wv.w };
                float za[4] = { zv.x, zv.y, zv.z, zv.w };
#pragma unroll
                for (int j = 0; j < 4; j++) {
                    float w2 = wa[j];
                    float zn2 = -2.0f * za[j];
                    float p1 = w2 * w2;
                    float e1 = fmaf(w2, w2, -p1);
                    float p2 = zn2 * w2;
                    float e2 = fmaf(zn2, w2, -p2);
                    ds_add(s, comp, p1);
                    ds_add(s, comp, p2);
                    ds_add(s, comp, e1);
                    ds_add(s, comp, e2);
                }
            }
            double q = (double)s + (double)comp;
            if (q < bq || (q == bq && k < best)) { bq = q; best = k; }
        }
    }
    g_idx[n] = best;
    dout[IDX_OFF + n] = (float)best;
}

// ---------------------------------------------------------------------------
// Scatter: float4 of consecutive hw per thread (4 gathers in flight),
// loss block-reduce + atomic, last-block ticket writes the loss scalar.
// ---------------------------------------------------------------------------
__global__ void k_scatter(const float* __restrict__ weight, float* __restrict__ dout) {
    int o4 = blockIdx.x * 256 + threadIdx.x;   // float4 index
    int o  = o4 * 4;
    int b  = o >> 17;
    int c  = (o >> 10) & 127;
    int hw = o & 1023;
    int n0 = (b << 10) | hw;

    float4 zt = *(const float4*)(g_znorm_t + o);
    float out[4], dsum = 0.0f;
#pragma unroll
    for (int j = 0; j < 4; j++) {
        int idx = g_idx[n0 + j] & (KCB - 1);
        float wv = weight[(size_t)idx * DIM + c];
        float z = (j == 0) ? zt.x : (j == 1) ? zt.y : (j == 2) ? zt.z : zt.w;
        float diff = __fsub_rn(wv, z);
        out[j] = __fadd_rn(z, diff);
        dsum = fmaf(diff, diff, dsum);
    }
    *(float4*)(dout + o) = make_float4(out[0], out[1], out[2], out[3]);

    __shared__ float wsum[8];
#pragma unroll
    for (int off = 16; off; off >>= 1) dsum += __shfl_down_sync(0xffffffffu, dsum, off);
    if ((threadIdx.x & 31) == 0) wsum[threadIdx.x >> 5] = dsum;
    __syncthreads();
    if (threadIdx.x < 8) {
        float v = wsum[threadIdx.x];
#pragma unroll
        for (int off = 4; off; off >>= 1) v += __shfl_down_sync(0xffu, v, off);
        if (threadIdx.x == 0) {
            atomicAdd(&g_lossacc, v);
            __threadfence();
            unsigned ticket = atomicAdd(&g_done, 1u);
            if (ticket == gridDim.x - 1) {
                g_done = 0;   // restore for next graph replay
                dout[LOSS_OFF] = 0.25f * atomicAdd(&g_lossacc, 0.0f) / (float)ZQ_ELEMS;
            }
        }
    }
}

// ---------------------------------------------------------------------------
extern "C" void kernel_launch(void* const* d_in, const int* in_sizes, int n_in,
                              void* d_out, int out_size) {
    const float* z = (const float*)d_in[0];
    const float* w = (const float*)d_in[1];
    float* out = (float*)d_out;

    cudaFuncSetAttribute(k_main_split, cudaFuncAttributeMaxDynamicSharedMemorySize, SM_TOTAL);

    k_prep<<<1152, 256>>>(z, w);                           // launch 0 (fused)
    k_main_split<<<N_CTAS, 256, SM_TOTAL>>>(out);          // launch 1
    k_merge<<<N_POS / 128, 128>>>(w, out);                 // launch 2
    k_scatter<<<ZQ_ELEMS / 4 / 256, 256>>>(w, out);        // launch 3 (incl. loss)
}